// round 8
// baseline (speedup 1.0000x reference)
#include <cuda_runtime.h>
#include <cuda_bf16.h>
#include <math.h>

#define A_   128
#define D_   128
#define DM1  127
#define MAXB 64
#define NB   4                 // batch elements per CTA
#define PB   (16 * A_ + 8)     // padded per-b partial region (floats)

// Packed T (bf16 probabilities). uint4 index:
//   u4 = ((d*16 + wt)*4 + kp)*32 + lane
// holds {T[d][8wt+2kp][4l..4l+3], T[d][8wt+2kp+1][4l..4l+3]}.
// Consecutive lanes -> consecutive uint4: warp LDG.128 = one 512B run.
__device__ uint2  g_T[(size_t)DM1 * A_ * A_ / 4];
// Emission table: {sigmoid(l), sigmoid(-l)} per (d,j).
__device__ float2 g_S2[D_ * A_];
// Initial-state probabilities.
__device__ float  g_pa1[A_];

// ---------------------------------------------------------------------------
// Prep A: row softmax of u_log_transition -> g_T (packed layout above).
// ---------------------------------------------------------------------------
__global__ void k_prepT(const float* __restrict__ u) {
    int w = threadIdx.x >> 5, lane = threadIdx.x & 31;
    int row = blockIdx.x * 8 + w;
    if (row >= DM1 * A_) return;
    float4 v4 = reinterpret_cast<const float4*>(u)[(size_t)row * 32 + lane];
    float m = fmaxf(fmaxf(v4.x, v4.y), fmaxf(v4.z, v4.w));
    #pragma unroll
    for (int o = 16; o > 0; o >>= 1) m = fmaxf(m, __shfl_xor_sync(0xffffffffu, m, o));
    float e0 = __expf(v4.x - m), e1 = __expf(v4.y - m);
    float e2 = __expf(v4.z - m), e3 = __expf(v4.w - m);
    float s = e0 + e1 + e2 + e3;
    #pragma unroll
    for (int o = 16; o > 0; o >>= 1) s += __shfl_xor_sync(0xffffffffu, s, o);
    float inv = 1.0f / s;
    __nv_bfloat162 p0 = __floats2bfloat162_rn(e0 * inv, e1 * inv);
    __nv_bfloat162 p1 = __floats2bfloat162_rn(e2 * inv, e3 * inv);
    uint2 ov;
    ov.x = *reinterpret_cast<unsigned int*>(&p0);
    ov.y = *reinterpret_cast<unsigned int*>(&p1);
    int d  = row >> 7;
    int k  = row & (A_ - 1);
    int wt = k >> 3;
    int kk = k & 7;
    size_t i2 = (((size_t)d * 16 + wt) * 4 + (kk >> 1)) * 32 + lane;
    g_T[i2 * 2 + (kk & 1)] = ov;
}

// ---------------------------------------------------------------------------
// Prep B: emission sigmoid table.
// ---------------------------------------------------------------------------
__global__ void k_prepS(const float* __restrict__ lpx) {
    int i = blockIdx.x * 256 + threadIdx.x;
    if (i < D_ * A_) {
        float l = lpx[i];
        g_S2[i] = make_float2(1.0f / (1.0f + __expf(-l)),
                              1.0f / (1.0f + __expf(l)));
    }
}

// ---------------------------------------------------------------------------
// Prep C: softmax of u_log_p_a1 -> g_pa1; writes log_p_a1 output tail.
// ---------------------------------------------------------------------------
__global__ void k_pa1(const float* __restrict__ u, float* __restrict__ out,
                      int base, int out_size) {
    __shared__ float sred[4];
    int t = threadIdx.x, lane = t & 31, w = t >> 5;
    float v = u[t];
    float m = v;
    #pragma unroll
    for (int o = 16; o > 0; o >>= 1) m = fmaxf(m, __shfl_xor_sync(0xffffffffu, m, o));
    if (lane == 0) sred[w] = m;
    __syncthreads();
    m = fmaxf(fmaxf(sred[0], sred[1]), fmaxf(sred[2], sred[3]));
    __syncthreads();
    float e = __expf(v - m);
    float s = e;
    #pragma unroll
    for (int o = 16; o > 0; o >>= 1) s += __shfl_xor_sync(0xffffffffu, s, o);
    if (lane == 0) sred[w] = s;
    __syncthreads();
    s = sred[0] + sred[1] + sred[2] + sred[3];
    float lp = v - m - logf(s);
    g_pa1[t] = __expf(lp);
    int idx = base + t;
    if (idx < out_size) out[idx] = lp;
}

// ---------------------------------------------------------------------------
// Main forward recurrence: 4 batch elements per CTA. grid = B/4, block = 512.
// Warp w owns k in [8w, 8w+8) for ALL 4 b's; the same T registers/unpacks
// feed all 4. Lane l: b = l>>3, j = 8w + (l&7); v[b][8w+(l&7)] lives in that
// lane's register; broadcast via SHFL. Combine keeps all 32 lanes busy.
// Two barriers per step (single partial buffer); rescale every 16 steps rides
// the second barrier.
// ---------------------------------------------------------------------------
__global__ void __launch_bounds__(512, 1) k_forward(const float* __restrict__ x,
                                                    float* __restrict__ out,
                                                    int out_size) {
    const int b0 = blockIdx.x * NB;
    const int t = threadIdx.x;
    const int w = t >> 5, lane = t & 31;
    const int myb = lane >> 3;
    const int jown = 8 * w + (lane & 7);

    __shared__ float part[NB * PB];
    __shared__ float s_red[16][NB];
    __shared__ float sx[NB][D_];

    // load x for 4 b's: t covers [b][d]
    sx[t >> 7][t & 127] = x[(b0 + (t >> 7)) * D_ + (t & 127)];
    __syncthreads();

    float v_reg, e_pref, acc = 0.f;
    {
        float2 s0 = g_S2[jown];
        v_reg = ((sx[myb][0] > 0.5f) ? s0.x : s0.y) * g_pa1[jown];
        float2 s1 = g_S2[A_ + jown];
        e_pref = (sx[myb][1] > 0.5f) ? s1.x : s1.y;
    }

    // per-(warp,lane) T base in uint4 units; +d*2048 per matrix; +kp*32
    const uint4* Tb = reinterpret_cast<const uint4*>(g_T) +
                      (size_t)w * 4 * 32 + lane;

    uint4 TA[4], TB[4];
    #pragma unroll
    for (int c = 0; c < 4; ++c) TA[c] = Tb[c * 32];    // d-matrix 0

#define PREFETCH_T(DST, DMAT) do {                                          \
        const uint4* _tp = Tb + (size_t)(DMAT) * 2048;                      \
        _Pragma("unroll")                                                   \
        for (int c = 0; c < 4; ++c) (DST)[c] = _tp[c * 32];                 \
    } while (0)

#define STEP(DD, TARR) do {                                                 \
        float a00 = 0.f, a01 = 0.f, a02 = 0.f, a03 = 0.f;                   \
        float a10 = 0.f, a11 = 0.f, a12 = 0.f, a13 = 0.f;                   \
        float a20 = 0.f, a21 = 0.f, a22 = 0.f, a23 = 0.f;                   \
        float a30 = 0.f, a31 = 0.f, a32 = 0.f, a33 = 0.f;                   \
        _Pragma("unroll")                                                   \
        for (int kp = 0; kp < 4; ++kp) {                                    \
            uint4 r = (TARR)[kp];                                           \
            float f0 = __uint_as_float(r.x << 16);                          \
            float f1 = __uint_as_float(r.x & 0xffff0000u);                  \
            float f2 = __uint_as_float(r.y << 16);                          \
            float f3 = __uint_as_float(r.y & 0xffff0000u);                  \
            float g0 = __uint_as_float(r.z << 16);                          \
            float g1 = __uint_as_float(r.z & 0xffff0000u);                  \
            float g2 = __uint_as_float(r.w << 16);                          \
            float g3 = __uint_as_float(r.w & 0xffff0000u);                  \
            float u0, u1;                                                   \
            u0 = __shfl_sync(0xffffffffu, v_reg, 2 * kp);                   \
            u1 = __shfl_sync(0xffffffffu, v_reg, 2 * kp + 1);               \
            a00 = fmaf(u0, f0, a00); a01 = fmaf(u0, f1, a01);               \
            a02 = fmaf(u0, f2, a02); a03 = fmaf(u0, f3, a03);               \
            a00 = fmaf(u1, g0, a00); a01 = fmaf(u1, g1, a01);               \
            a02 = fmaf(u1, g2, a02); a03 = fmaf(u1, g3, a03);               \
            u0 = __shfl_sync(0xffffffffu, v_reg, 8 + 2 * kp);               \
            u1 = __shfl_sync(0xffffffffu, v_reg, 9 + 2 * kp);               \
            a10 = fmaf(u0, f0, a10); a11 = fmaf(u0, f1, a11);               \
            a12 = fmaf(u0, f2, a12); a13 = fmaf(u0, f3, a13);               \
            a10 = fmaf(u1, g0, a10); a11 = fmaf(u1, g1, a11);               \
            a12 = fmaf(u1, g2, a12); a13 = fmaf(u1, g3, a13);               \
            u0 = __shfl_sync(0xffffffffu, v_reg, 16 + 2 * kp);              \
            u1 = __shfl_sync(0xffffffffu, v_reg, 17 + 2 * kp);              \
            a20 = fmaf(u0, f0, a20); a21 = fmaf(u0, f1, a21);               \
            a22 = fmaf(u0, f2, a22); a23 = fmaf(u0, f3, a23);               \
            a20 = fmaf(u1, g0, a20); a21 = fmaf(u1, g1, a21);               \
            a22 = fmaf(u1, g2, a22); a23 = fmaf(u1, g3, a23);               \
            u0 = __shfl_sync(0xffffffffu, v_reg, 24 + 2 * kp);              \
            u1 = __shfl_sync(0xffffffffu, v_reg, 25 + 2 * kp);              \
            a30 = fmaf(u0, f0, a30); a31 = fmaf(u0, f1, a31);               \
            a32 = fmaf(u0, f2, a32); a33 = fmaf(u0, f3, a33);               \
            a30 = fmaf(u1, g0, a30); a31 = fmaf(u1, g1, a31);               \
            a32 = fmaf(u1, g2, a32); a33 = fmaf(u1, g3, a33);               \
        }                                                                   \
        float* pw = &part[w * A_ + 4 * lane];                               \
        *reinterpret_cast<float4*>(pw + 0 * PB) = make_float4(a00, a01, a02, a03); \
        *reinterpret_cast<float4*>(pw + 1 * PB) = make_float4(a10, a11, a12, a13); \
        *reinterpret_cast<float4*>(pw + 2 * PB) = make_float4(a20, a21, a22, a23); \
        *reinterpret_cast<float4*>(pw + 3 * PB) = make_float4(a30, a31, a32, a33); \
        __syncthreads();                                                    \
        {                                                                   \
            const float* pb = &part[myb * PB + jown];                       \
            float p0 = pb[0 * A_],  p1 = pb[1 * A_];                        \
            float p2 = pb[2 * A_],  p3 = pb[3 * A_];                        \
            float p4 = pb[4 * A_],  p5 = pb[5 * A_];                        \
            float p6 = pb[6 * A_],  p7 = pb[7 * A_];                        \
            float p8 = pb[8 * A_],  p9 = pb[9 * A_];                        \
            float pa = pb[10 * A_], pc = pb[11 * A_];                       \
            float pd = pb[12 * A_], pe = pb[13 * A_];                       \
            float pf = pb[14 * A_], pg = pb[15 * A_];                       \
            float s = (((p0 + p1) + (p2 + p3)) + ((p4 + p5) + (p6 + p7)))   \
                    + (((p8 + p9) + (pa + pc)) + ((pd + pe) + (pf + pg)));  \
            v_reg = s * e_pref;                                             \
            int dn = ((DD) + 1 < D_) ? (DD) + 1 : (DD);                     \
            float2 sn = g_S2[dn * A_ + jown];                               \
            e_pref = (sx[myb][dn] > 0.5f) ? sn.x : sn.y;                    \
        }                                                                   \
        const bool resc = (((DD) & 15) == 15) && ((DD) != DM1);             \
        if (resc) {                                                         \
            float m = v_reg;                                                \
            m = fmaxf(m, __shfl_xor_sync(0xffffffffu, m, 4, 8));            \
            m = fmaxf(m, __shfl_xor_sync(0xffffffffu, m, 2, 8));            \
            m = fmaxf(m, __shfl_xor_sync(0xffffffffu, m, 1, 8));            \
            if ((lane & 7) == 0) s_red[w][myb] = m;                         \
        }                                                                   \
        __syncthreads();   /* WAR on part; also publishes s_red */          \
        if (resc) {                                                         \
            float mm = fmaxf(                                               \
                fmaxf(fmaxf(s_red[0][myb],  s_red[1][myb]),                 \
                      fmaxf(s_red[2][myb],  s_red[3][myb])),                \
                fmaxf(fmaxf(s_red[4][myb],  s_red[5][myb]),                 \
                      fmaxf(s_red[6][myb],  s_red[7][myb])));               \
            mm = fmaxf(mm, fmaxf(                                           \
                fmaxf(fmaxf(s_red[8][myb],  s_red[9][myb]),                 \
                      fmaxf(s_red[10][myb], s_red[11][myb])),               \
                fmaxf(fmaxf(s_red[12][myb], s_red[13][myb]),                \
                      fmaxf(s_red[14][myb], s_red[15][myb]))));             \
            e_pref *= (1.0f / mm);                                          \
            acc += __logf(mm);                                              \
        }                                                                   \
    } while (0)

    // steps d = 1 .. 126 in pairs, double-buffered T
    for (int i = 1; i < DM1; i += 2) {
        PREFETCH_T(TB, i);                           // T[i] used at step i+1
        STEP(i, TA);
        PREFETCH_T(TA, (i + 1 < DM1) ? (i + 1) : i); // T[i+1] used at step i+2
        STEP(i + 1, TB);
    }
    STEP(DM1, TA);                                   // d=127 uses T[126]

#undef STEP
#undef PREFETCH_T

    // final: log_px[b] = acc + log(sum_j v_final[j]), per 8-lane group
    float sv = v_reg;
    sv += __shfl_xor_sync(0xffffffffu, sv, 4, 8);
    sv += __shfl_xor_sync(0xffffffffu, sv, 2, 8);
    sv += __shfl_xor_sync(0xffffffffu, sv, 1, 8);
    if ((lane & 7) == 0) s_red[w][myb] = sv;
    __syncthreads();
    float tot = (((s_red[0][myb]  + s_red[1][myb])  + (s_red[2][myb]  + s_red[3][myb]))
              +  ((s_red[4][myb]  + s_red[5][myb])  + (s_red[6][myb]  + s_red[7][myb])))
              + (((s_red[8][myb]  + s_red[9][myb])  + (s_red[10][myb] + s_red[11][myb]))
              +  ((s_red[12][myb] + s_red[13][myb]) + (s_red[14][myb] + s_red[15][myb])));
    float res = acc + __logf(tot);
    int idx = (b0 + myb) * A_ + jown;
    if (idx < out_size) out[idx] = res;
}

// ---------------------------------------------------------------------------
extern "C" void kernel_launch(void* const* d_in, const int* in_sizes, int n_in,
                              void* d_out, int out_size) {
    const float* x     = (const float*)d_in[0];   // [B, D]
    const float* u_pa1 = (const float*)d_in[1];   // [1,1,1,A]
    const float* u_T   = (const float*)d_in[2];   // [D-1, A, A]
    const float* lpx   = (const float*)d_in[3];   // [1, D, 1, A]
    float* out = (float*)d_out;

    int B = in_sizes[0] / D_;
    if (B > MAXB) B = MAXB;

    k_prepT<<<(DM1 * A_ + 7) / 8, 256>>>(u_T);
    k_prepS<<<(D_ * A_ + 255) / 256, 256>>>(lpx);
    k_pa1<<<1, 128>>>(u_pa1, out, B * A_, out_size);

    k_forward<<<(B + NB - 1) / NB, 512>>>(x, out, out_size);
}

// round 9
// speedup vs baseline: 1.4601x; 1.4601x over previous
#include <cuda_runtime.h>
#include <cuda_bf16.h>
#include <math.h>

#define A_   128
#define D_   128
#define DM1  127
#define MAXB 64

// Packed T (bf16 probabilities), viewed as uint4:
//   u4 = ((d*16 + w)*4 + c)*32 + lane,   w = jh*8 + kg
// holds 8 bf16: words rr=0..3 cover k = 16kg + 4c + rr; each word packs
// {j = 64jh + 2*lane (low 16), j+1 (high 16)}.
__device__ uint4  g_T4[(size_t)DM1 * 2048];
// Emission table: {sigmoid(l), sigmoid(-l)} per (d,j).
__device__ float2 g_S2[D_ * A_];
// Initial-state probabilities.
__device__ float  g_pa1[A_];

// ---------------------------------------------------------------------------
// Prep A: row softmax of u_log_transition -> g_T4 (packed layout above).
// One warp per (d,k) row; lane covers j-quad 4*lane..4*lane+3.
// ---------------------------------------------------------------------------
__global__ void k_prepT(const float* __restrict__ u) {
    int w = threadIdx.x >> 5, lane = threadIdx.x & 31;
    int row = blockIdx.x * 8 + w;
    if (row >= DM1 * A_) return;
    float4 v4 = reinterpret_cast<const float4*>(u)[(size_t)row * 32 + lane];
    float m = fmaxf(fmaxf(v4.x, v4.y), fmaxf(v4.z, v4.w));
    #pragma unroll
    for (int o = 16; o > 0; o >>= 1) m = fmaxf(m, __shfl_xor_sync(0xffffffffu, m, o));
    float e0 = __expf(v4.x - m), e1 = __expf(v4.y - m);
    float e2 = __expf(v4.z - m), e3 = __expf(v4.w - m);
    float s = e0 + e1 + e2 + e3;
    #pragma unroll
    for (int o = 16; o > 0; o >>= 1) s += __shfl_xor_sync(0xffffffffu, s, o);
    float inv = 1.0f / s;
    float pv[4] = {e0 * inv, e1 * inv, e2 * inv, e3 * inv};

    int d  = row >> 7;
    int k  = row & (A_ - 1);
    int kg = k >> 4;
    int cc = (k & 15) >> 2;
    int rr = k & 3;
    __nv_bfloat16* tb = reinterpret_cast<__nv_bfloat16*>(g_T4);
    #pragma unroll
    for (int qq = 0; qq < 4; ++qq) {
        int j  = 4 * lane + qq;
        int jh = j >> 6;
        int lt = (j & 63) >> 1;
        int q  = j & 1;
        int wrp = jh * 8 + kg;
        size_t bidx = ((((size_t)d * 16 + wrp) * 4 + cc) * 32 + lt) * 8 + rr * 2 + q;
        tb[bidx] = __float2bfloat16_rn(pv[qq]);
    }
}

// ---------------------------------------------------------------------------
// Prep B: emission sigmoid table.
// ---------------------------------------------------------------------------
__global__ void k_prepS(const float* __restrict__ lpx) {
    int i = blockIdx.x * 256 + threadIdx.x;
    if (i < D_ * A_) {
        float l = lpx[i];
        g_S2[i] = make_float2(1.0f / (1.0f + __expf(-l)),
                              1.0f / (1.0f + __expf(l)));
    }
}

// ---------------------------------------------------------------------------
// Prep C: softmax of u_log_p_a1 -> g_pa1; writes log_p_a1 output tail.
// ---------------------------------------------------------------------------
__global__ void k_pa1(const float* __restrict__ u, float* __restrict__ out,
                      int base, int out_size) {
    __shared__ float sred[4];
    int t = threadIdx.x, lane = t & 31, w = t >> 5;
    float v = u[t];
    float m = v;
    #pragma unroll
    for (int o = 16; o > 0; o >>= 1) m = fmaxf(m, __shfl_xor_sync(0xffffffffu, m, o));
    if (lane == 0) sred[w] = m;
    __syncthreads();
    m = fmaxf(fmaxf(sred[0], sred[1]), fmaxf(sred[2], sred[3]));
    __syncthreads();
    float e = __expf(v - m);
    float s = e;
    #pragma unroll
    for (int o = 16; o > 0; o >>= 1) s += __shfl_xor_sync(0xffffffffu, s, o);
    if (lane == 0) sred[w] = s;
    __syncthreads();
    s = sred[0] + sred[1] + sred[2] + sred[3];
    float lp = v - m - logf(s);
    g_pa1[t] = __expf(lp);
    int idx = base + t;
    if (idx < out_size) out[idx] = lp;
}

// ---------------------------------------------------------------------------
// Main forward recurrence. grid = B, block = 512 (16 warps).
// Warp w = jh*8+kg owns k in [16kg,16kg+16), j in [64jh,64jh+64);
// lane computes j-pair (jp, jp+1), jp = 64jh + 2*lane: 32 FMA/lane/step.
// Partials part[kg][j] (stride 132): one STS.64 per lane; 8 partials per j.
// Owners (threads 0..127, j = t) combine, apply emission, write v_sh (double-
// buffered). v read back by 4 broadcast LDS.128 per warp. 2 barriers/step.
// Rescale every 16 steps on owners, folded into e_pref (rides barrier 2).
// ---------------------------------------------------------------------------
__global__ void __launch_bounds__(512, 1) k_forward(const float* __restrict__ x,
                                                    float* __restrict__ out,
                                                    int out_size) {
    const int b = blockIdx.x;
    const int t = threadIdx.x;
    const int w = t >> 5, lane = t & 31;
    const int kg = w & 7, jh = w >> 3;
    const int kb = kg * 16;
    const int jp = (jh << 6) + 2 * lane;

    __shared__ __align__(16) float v_sh[2][A_];
    __shared__ float part[8][132];
    __shared__ float s_red[4];
    __shared__ float sx[D_];

    const bool owner = (t < A_);
    const int j = t & (A_ - 1);

    if (t < D_) sx[t] = x[b * D_ + t];
    __syncthreads();

    float e_pref = 0.f, acc = 0.f, vfin = 0.f;
    if (owner) {
        float2 s0 = g_S2[j];
        v_sh[0][j] = ((sx[0] > 0.5f) ? s0.x : s0.y) * g_pa1[j];
        float2 s1 = g_S2[A_ + j];
        e_pref = (sx[1] > 0.5f) ? s1.x : s1.y;
    }
    __syncthreads();   // v_sh[0] ready

    // per-(warp,lane) T base in uint4 units; +d*2048 per matrix; +c*32
    const uint4* Tb = g_T4 + (size_t)w * 128 + lane;

    uint4 TA[4], TB[4];
    #pragma unroll
    for (int c = 0; c < 4; ++c) TA[c] = Tb[c * 32];    // d-matrix 0

#define PREFETCH_T(DST, DMAT) do {                                          \
        const uint4* _tp = Tb + (size_t)(DMAT) * 2048;                      \
        _Pragma("unroll")                                                   \
        for (int c = 0; c < 4; ++c) (DST)[c] = _tp[c * 32];                 \
    } while (0)

#define UNPK(R, VV) do {                                                    \
        a0 = fmaf(__uint_as_float((R).x << 16),          (VV).x, a0);       \
        a1 = fmaf(__uint_as_float((R).x & 0xffff0000u),  (VV).x, a1);       \
        a0 = fmaf(__uint_as_float((R).y << 16),          (VV).y, a0);       \
        a1 = fmaf(__uint_as_float((R).y & 0xffff0000u),  (VV).y, a1);       \
        a0 = fmaf(__uint_as_float((R).z << 16),          (VV).z, a0);       \
        a1 = fmaf(__uint_as_float((R).z & 0xffff0000u),  (VV).z, a1);       \
        a0 = fmaf(__uint_as_float((R).w << 16),          (VV).w, a0);       \
        a1 = fmaf(__uint_as_float((R).w & 0xffff0000u),  (VV).w, a1);       \
    } while (0)

#define STEP(DD, TARR) do {                                                 \
        const int rb = ((DD) + 1) & 1, wb = (DD) & 1;                       \
        float4 vv0 = *reinterpret_cast<const float4*>(&v_sh[rb][kb]);       \
        float4 vv1 = *reinterpret_cast<const float4*>(&v_sh[rb][kb + 4]);   \
        float4 vv2 = *reinterpret_cast<const float4*>(&v_sh[rb][kb + 8]);   \
        float4 vv3 = *reinterpret_cast<const float4*>(&v_sh[rb][kb + 12]);  \
        float a0 = 0.f, a1 = 0.f;                                           \
        UNPK((TARR)[0], vv0);                                               \
        UNPK((TARR)[1], vv1);                                               \
        UNPK((TARR)[2], vv2);                                               \
        UNPK((TARR)[3], vv3);                                               \
        *reinterpret_cast<float2*>(&part[kg][jp]) = make_float2(a0, a1);    \
        __syncthreads();                                                    \
        const bool resc = (((DD) & 15) == 15) && ((DD) != DM1);             \
        if (owner) {                                                        \
            float p = ((part[0][j] + part[1][j]) + (part[2][j] + part[3][j])) \
                    + ((part[4][j] + part[5][j]) + (part[6][j] + part[7][j])); \
            float val = p * e_pref;                                         \
            v_sh[wb][j] = val;                                              \
            vfin = val;                                                     \
            int dn = ((DD) + 1 < D_) ? (DD) + 1 : (DD);                     \
            float2 sn = g_S2[dn * A_ + j];                                  \
            e_pref = (sx[dn] > 0.5f) ? sn.x : sn.y;                         \
            if (resc) {                                                     \
                float m = val;                                              \
                m = fmaxf(m, __shfl_xor_sync(0xffffffffu, m, 16));          \
                m = fmaxf(m, __shfl_xor_sync(0xffffffffu, m, 8));           \
                m = fmaxf(m, __shfl_xor_sync(0xffffffffu, m, 4));           \
                m = fmaxf(m, __shfl_xor_sync(0xffffffffu, m, 2));           \
                m = fmaxf(m, __shfl_xor_sync(0xffffffffu, m, 1));           \
                if (lane == 0) s_red[w] = m;                                \
            }                                                               \
        }                                                                   \
        __syncthreads();   /* v_sh[wb] + s_red published; part reusable */  \
        if (owner && resc) {                                                \
            float mm = fmaxf(fmaxf(s_red[0], s_red[1]),                     \
                             fmaxf(s_red[2], s_red[3]));                    \
            e_pref *= (1.0f / mm);                                          \
            acc += __logf(mm);                                              \
        }                                                                   \
    } while (0)

    // steps d = 1 .. 126 in pairs, double-buffered T
    for (int i = 1; i < DM1; i += 2) {
        PREFETCH_T(TB, i);                           // matrix i, for step i+1
        STEP(i, TA);
        PREFETCH_T(TA, (i + 1 < DM1) ? (i + 1) : i); // matrix i+1, step i+2
        STEP(i + 1, TB);
    }
    STEP(DM1, TA);                                   // d=127 uses matrix 126

#undef STEP
#undef UNPK
#undef PREFETCH_T

    // final: log_px[b] = acc + log(sum_j v_final[j])  (owners hold vfin)
    if (owner) {
        float sv = vfin;
        #pragma unroll
        for (int o = 16; o > 0; o >>= 1)
            sv += __shfl_xor_sync(0xffffffffu, sv, o);
        if (lane == 0) s_red[w] = sv;
    }
    __syncthreads();
    if (owner) {
        float tot = (s_red[0] + s_red[1]) + (s_red[2] + s_red[3]);
        float res = acc + __logf(tot);
        int idx = b * A_ + j;
        if (idx < out_size) out[idx] = res;
    }
}

// ---------------------------------------------------------------------------
extern "C" void kernel_launch(void* const* d_in, const int* in_sizes, int n_in,
                              void* d_out, int out_size) {
    const float* x     = (const float*)d_in[0];   // [B, D]
    const float* u_pa1 = (const float*)d_in[1];   // [1,1,1,A]
    const float* u_T   = (const float*)d_in[2];   // [D-1, A, A]
    const float* lpx   = (const float*)d_in[3];   // [1, D, 1, A]
    float* out = (float*)d_out;

    int B = in_sizes[0] / D_;
    if (B > MAXB) B = MAXB;

    k_prepT<<<(DM1 * A_ + 7) / 8, 256>>>(u_T);
    k_prepS<<<(D_ * A_ + 255) / 256, 256>>>(lpx);
    k_pa1<<<1, 128>>>(u_pa1, out, B * A_, out_size);

    k_forward<<<B, 512>>>(x, out, out_size);
}

// round 10
// speedup vs baseline: 1.6500x; 1.1301x over previous
#include <cuda_runtime.h>
#include <cuda_bf16.h>
#include <math.h>

#define A_   128
#define D_   128
#define DM1  127
#define MAXB 64
#define VP   36          // v_sh quarter pitch (floats) — bank-swizzle

// Packed T (bf16). uint4 index: u4 = ((d*16 + w)*4 + c)*32 + lane.
// Lane's uint4 c holds k = 32*(lane>>3) + 8c + r (r=0..7), j = 8w + (lane&7).
// Consecutive lanes -> consecutive uint4 (coalesced LDG.128).
__device__ uint4  g_T4[(size_t)DM1 * 2048];
// Emission table: {sigmoid(l), sigmoid(-l)} per (d,j).
__device__ float2 g_S2[D_ * A_];
// Initial-state probabilities.
__device__ float  g_pa1[A_];

// ---------------------------------------------------------------------------
// Prep A: row softmax of u_log_transition -> g_T4 (layout above).
// One warp per (d,k) row; lane covers j-quad 4*lane..4*lane+3.
// ---------------------------------------------------------------------------
__global__ void k_prepT(const float* __restrict__ u) {
    int w = threadIdx.x >> 5, lane = threadIdx.x & 31;
    int row = blockIdx.x * 8 + w;
    if (row >= DM1 * A_) return;
    float4 v4 = reinterpret_cast<const float4*>(u)[(size_t)row * 32 + lane];
    float m = fmaxf(fmaxf(v4.x, v4.y), fmaxf(v4.z, v4.w));
    #pragma unroll
    for (int o = 16; o > 0; o >>= 1) m = fmaxf(m, __shfl_xor_sync(0xffffffffu, m, o));
    float e0 = __expf(v4.x - m), e1 = __expf(v4.y - m);
    float e2 = __expf(v4.z - m), e3 = __expf(v4.w - m);
    float s = e0 + e1 + e2 + e3;
    #pragma unroll
    for (int o = 16; o > 0; o >>= 1) s += __shfl_xor_sync(0xffffffffu, s, o);
    float inv = 1.0f / s;
    float pv[4] = {e0 * inv, e1 * inv, e2 * inv, e3 * inv};

    int d = row >> 7;
    int k = row & (A_ - 1);
    int kq = k >> 5;
    int c  = (k & 31) >> 3;
    int r  = k & 7;
    __nv_bfloat16* tb = reinterpret_cast<__nv_bfloat16*>(g_T4);
    #pragma unroll
    for (int qq = 0; qq < 4; ++qq) {
        int j  = 4 * lane + qq;
        int wt = j >> 3;
        int ln = (j & 7) | (kq << 3);
        size_t bidx = ((((size_t)d * 16 + wt) * 4 + c) * 32 + ln) * 8 + r;
        tb[bidx] = __float2bfloat16_rn(pv[qq]);
    }
}

// ---------------------------------------------------------------------------
// Prep B: emission sigmoid table.
// ---------------------------------------------------------------------------
__global__ void k_prepS(const float* __restrict__ lpx) {
    int i = blockIdx.x * 256 + threadIdx.x;
    if (i < D_ * A_) {
        float l = lpx[i];
        g_S2[i] = make_float2(1.0f / (1.0f + __expf(-l)),
                              1.0f / (1.0f + __expf(l)));
    }
}

// ---------------------------------------------------------------------------
// Prep C: softmax of u_log_p_a1 -> g_pa1; writes log_p_a1 output tail.
// ---------------------------------------------------------------------------
__global__ void k_pa1(const float* __restrict__ u, float* __restrict__ out,
                      int base, int out_size) {
    __shared__ float sred[4];
    int t = threadIdx.x, lane = t & 31, w = t >> 5;
    float v = u[t];
    float m = v;
    #pragma unroll
    for (int o = 16; o > 0; o >>= 1) m = fmaxf(m, __shfl_xor_sync(0xffffffffu, m, o));
    if (lane == 0) sred[w] = m;
    __syncthreads();
    m = fmaxf(fmaxf(sred[0], sred[1]), fmaxf(sred[2], sred[3]));
    __syncthreads();
    float e = __expf(v - m);
    float s = e;
    #pragma unroll
    for (int o = 16; o > 0; o >>= 1) s += __shfl_xor_sync(0xffffffffu, s, o);
    if (lane == 0) sred[w] = s;
    __syncthreads();
    s = sred[0] + sred[1] + sred[2] + sred[3];
    float lp = v - m - logf(s);
    g_pa1[t] = __expf(lp);
    int idx = base + t;
    if (idx < out_size) out[idx] = lp;
}

// ---------------------------------------------------------------------------
// Main forward recurrence. grid = B, block = 512 (16 warps).
// Warp w owns j in [8w, 8w+8) over ALL k. Lane l: j = 8w + (l&7),
// k-quarter = l>>3. 32 FMA/lane in 2 chains; combine via 2 shfl_xor (8,16);
// writer lanes (l<8) STS v_new. ONE barrier per step. v bank-swizzled
// (quarter pitch VP=36 floats) for conflict-free 4-address LDS.128.
// T double-buffered (4 uint4). Rescale every 16 steps rides the barrier.
// ---------------------------------------------------------------------------
__global__ void __launch_bounds__(512, 1) k_forward(const float* __restrict__ x,
                                                    float* __restrict__ out,
                                                    int out_size) {
    const int b = blockIdx.x;
    const int t = threadIdx.x;
    const int w = t >> 5, lane = t & 31;
    const int jown = 8 * w + (lane & 7);
    const int kq = lane >> 3;
    const int vq = kq * VP;
    const bool writer = (lane < 8);

    __shared__ __align__(16) float v_sh[2][4 * VP];
    __shared__ float s_red[16];
    __shared__ float sx[D_];

    if (t < D_) sx[t] = x[b * D_ + t];
    __syncthreads();

    float e_pref, acc = 0.f;
    {
        float2 s0 = g_S2[jown];
        float v0 = ((sx[0] > 0.5f) ? s0.x : s0.y) * g_pa1[jown];
        if (writer) v_sh[0][(jown >> 5) * VP + (jown & 31)] = v0;
        float2 s1 = g_S2[A_ + jown];
        e_pref = (sx[1] > 0.5f) ? s1.x : s1.y;
    }
    __syncthreads();   // v_sh[0] ready

    // per-(warp,lane) T base in uint4 units; +d*2048 per matrix; +c*32
    const uint4* Tb = g_T4 + (size_t)w * 128 + lane;

    uint4 TA[4], TB[4];
    #pragma unroll
    for (int c = 0; c < 4; ++c) TA[c] = Tb[c * 32];    // d-matrix 0

    float vfin = 0.f;

#define PREFETCH_T(DST, DMAT) do {                                          \
        const uint4* _tp = Tb + (size_t)(DMAT) * 2048;                      \
        _Pragma("unroll")                                                   \
        for (int c = 0; c < 4; ++c) (DST)[c] = _tp[c * 32];                 \
    } while (0)

// 8 FMAs of chunk c into ACC: k = 32kq + 8c + (0..7)
#define CHUNK(R, OFF, ACC) do {                                             \
        float4 va = *reinterpret_cast<const float4*>(&vr[(OFF)]);           \
        float4 vb = *reinterpret_cast<const float4*>(&vr[(OFF) + 4]);       \
        ACC = fmaf(__uint_as_float((R).x << 16),         va.x, ACC);        \
        ACC = fmaf(__uint_as_float((R).x & 0xffff0000u), va.y, ACC);        \
        ACC = fmaf(__uint_as_float((R).y << 16),         va.z, ACC);        \
        ACC = fmaf(__uint_as_float((R).y & 0xffff0000u), va.w, ACC);        \
        ACC = fmaf(__uint_as_float((R).z << 16),         vb.x, ACC);        \
        ACC = fmaf(__uint_as_float((R).z & 0xffff0000u), vb.y, ACC);        \
        ACC = fmaf(__uint_as_float((R).w << 16),         vb.z, ACC);        \
        ACC = fmaf(__uint_as_float((R).w & 0xffff0000u), vb.w, ACC);        \
    } while (0)

#define STEP(DD, TARR) do {                                                 \
        const int rb = ((DD) + 1) & 1, wb = (DD) & 1;                       \
        const float* vr = &v_sh[rb][vq];                                    \
        float acc0 = 0.f, acc1 = 0.f;                                       \
        CHUNK((TARR)[0], 0,  acc0);                                         \
        CHUNK((TARR)[1], 8,  acc1);                                         \
        CHUNK((TARR)[2], 16, acc0);                                         \
        CHUNK((TARR)[3], 24, acc1);                                         \
        float sum = acc0 + acc1;                                            \
        sum += __shfl_xor_sync(0xffffffffu, sum, 8);                        \
        sum += __shfl_xor_sync(0xffffffffu, sum, 16);                       \
        float val = sum * e_pref;                                           \
        if (writer) v_sh[wb][(jown >> 5) * VP + (jown & 31)] = val;         \
        vfin = val;                                                         \
        {   /* prefetch emission for next step (all lanes, broadcast) */    \
            int dn = ((DD) + 1 < D_) ? (DD) + 1 : (DD);                     \
            float2 sn = g_S2[dn * A_ + jown];                               \
            e_pref = (sx[dn] > 0.5f) ? sn.x : sn.y;                         \
        }                                                                   \
        const bool resc = (((DD) & 15) == 15) && ((DD) != DM1);             \
        if (resc) {                                                         \
            float m = val;                                                  \
            m = fmaxf(m, __shfl_xor_sync(0xffffffffu, m, 1));               \
            m = fmaxf(m, __shfl_xor_sync(0xffffffffu, m, 2));               \
            m = fmaxf(m, __shfl_xor_sync(0xffffffffu, m, 4));               \
            if (lane == 0) s_red[w] = m;                                    \
        }                                                                   \
        __syncthreads();   /* publishes v_sh[wb] (+ s_red on resc steps) */ \
        if (resc) {                                                         \
            float mm = fmaxf(                                               \
                fmaxf(fmaxf(s_red[0],  s_red[1]),  fmaxf(s_red[2],  s_red[3])),  \
                fmaxf(fmaxf(s_red[4],  s_red[5]),  fmaxf(s_red[6],  s_red[7]))); \
            mm = fmaxf(mm, fmaxf(                                           \
                fmaxf(fmaxf(s_red[8],  s_red[9]),  fmaxf(s_red[10], s_red[11])), \
                fmaxf(fmaxf(s_red[12], s_red[13]), fmaxf(s_red[14], s_red[15])))); \
            e_pref *= (1.0f / mm);                                          \
            acc += __logf(mm);                                              \
        }                                                                   \
    } while (0)

    // steps d = 1 .. 126 in pairs, double-buffered T
    for (int i = 1; i < DM1; i += 2) {
        PREFETCH_T(TB, i);                           // matrix i, for step i+1
        STEP(i, TA);
        PREFETCH_T(TA, (i + 1 < DM1) ? (i + 1) : i); // matrix i+1, step i+2
        STEP(i + 1, TB);
    }
    STEP(DM1, TA);                                   // d=127 uses matrix 126

#undef STEP
#undef CHUNK
#undef PREFETCH_T

    // final: log_px[b] = acc + log(sum_j v_final[j]).
    // Each group-of-8 lanes holds the warp's 8 j-values; sum within group.
    float sv = vfin;
    sv += __shfl_xor_sync(0xffffffffu, sv, 1);
    sv += __shfl_xor_sync(0xffffffffu, sv, 2);
    sv += __shfl_xor_sync(0xffffffffu, sv, 4);
    if (lane == 0) s_red[w] = sv;
    __syncthreads();
    float tot = (((s_red[0]  + s_red[1])  + (s_red[2]  + s_red[3]))
              +  ((s_red[4]  + s_red[5])  + (s_red[6]  + s_red[7])))
              + (((s_red[8]  + s_red[9])  + (s_red[10] + s_red[11]))
              +  ((s_red[12] + s_red[13]) + (s_red[14] + s_red[15])));
    float res = acc + __logf(tot);
    if (writer) {
        int idx = b * A_ + jown;
        if (idx < out_size) out[idx] = res;
    }
}

// ---------------------------------------------------------------------------
extern "C" void kernel_launch(void* const* d_in, const int* in_sizes, int n_in,
                              void* d_out, int out_size) {
    const float* x     = (const float*)d_in[0];   // [B, D]
    const float* u_pa1 = (const float*)d_in[1];   // [1,1,1,A]
    const float* u_T   = (const float*)d_in[2];   // [D-1, A, A]
    const float* lpx   = (const float*)d_in[3];   // [1, D, 1, A]
    float* out = (float*)d_out;

    int B = in_sizes[0] / D_;
    if (B > MAXB) B = MAXB;

    k_prepT<<<(DM1 * A_ + 7) / 8, 256>>>(u_T);
    k_prepS<<<(D_ * A_ + 255) / 256, 256>>>(lpx);
    k_pa1<<<1, 128>>>(u_pa1, out, B * A_, out_size);

    k_forward<<<B, 512>>>(x, out, out_size);
}

// round 11
// speedup vs baseline: 1.8294x; 1.1087x over previous
#include <cuda_runtime.h>
#include <cuda_bf16.h>
#include <math.h>

#define A_   128
#define D_   128
#define DM1  127
#define MAXB 64
#define VP   36          // v_sh quarter pitch (floats) — bank-swizzle
#define NSTEP 64         // 63 fused pair-steps + 1 tail step

// Fused transition matrices, bf16, packed for the forward kernel.
// Slot s (0..125): pair p = s>>1, variant x = s&1 : M_p[x] = T_2p diag(e_{2p+1,x}) T_{2p+1}
// Slot 126: plain T[126] (tail step).
// Packing (uint4 units): u4 = ((slot*16 + w)*4 + c)*32 + lane, lane's uint4 c
// holds k = 32*(lane>>3) + 8c + r (r=0..7), j = 8w + (lane&7).
__device__ uint4  g_M4[(size_t)127 * 2048];
// fp32 softmax of u_log_transition (scratch for the fuse GEMMs): [d][k][j].
__device__ float  g_Tf[(size_t)DM1 * A_ * A_];
// Emission table: {sigmoid(l), sigmoid(-l)} = {p(x=1), p(x=0)} per (d,j).
__device__ float2 g_S2[D_ * A_];
// Initial-state probabilities.
__device__ float  g_pa1[A_];

// ---------------------------------------------------------------------------
// f32x2 packed-FMA helpers (sm_103a FFMA2 — only reachable via PTX).
// ---------------------------------------------------------------------------
#define PACK_F32X2(out, lo, hi) \
    asm("mov.b64 %0, {%1, %2};" : "=l"(out) : "f"(lo), "f"(hi))
#define UNPACK_F32X2(lo, hi, in) \
    asm("mov.b64 {%0, %1}, %2;" : "=f"(lo), "=f"(hi) : "l"(in))
#define FMA_F32X2(acc, a, b) \
    asm("fma.rn.f32x2 %0, %1, %2, %0;" : "+l"(acc) : "l"(a), "l"(b))

// ---------------------------------------------------------------------------
// Prep A: row softmax of u_log_transition -> g_Tf (fp32); slot 126 of g_M4
// gets T[126] packed directly. One warp per (d,k) row.
// ---------------------------------------------------------------------------
__global__ void k_prepT(const float* __restrict__ u) {
    int w = threadIdx.x >> 5, lane = threadIdx.x & 31;
    int row = blockIdx.x * 8 + w;
    if (row >= DM1 * A_) return;
    float4 v4 = reinterpret_cast<const float4*>(u)[(size_t)row * 32 + lane];
    float m = fmaxf(fmaxf(v4.x, v4.y), fmaxf(v4.z, v4.w));
    #pragma unroll
    for (int o = 16; o > 0; o >>= 1) m = fmaxf(m, __shfl_xor_sync(0xffffffffu, m, o));
    float e0 = __expf(v4.x - m), e1 = __expf(v4.y - m);
    float e2 = __expf(v4.z - m), e3 = __expf(v4.w - m);
    float s = e0 + e1 + e2 + e3;
    #pragma unroll
    for (int o = 16; o > 0; o >>= 1) s += __shfl_xor_sync(0xffffffffu, s, o);
    float inv = 1.0f / s;
    float pv[4] = {e0 * inv, e1 * inv, e2 * inv, e3 * inv};

    reinterpret_cast<float4*>(g_Tf)[(size_t)row * 32 + lane] =
        make_float4(pv[0], pv[1], pv[2], pv[3]);

    int d = row >> 7;
    if (d == 126) {                // pack tail matrix into g_M4 slot 126
        int k = row & (A_ - 1);
        int c = (k & 31) >> 3;
        int r = k & 7;
        int kq = k >> 5;
        __nv_bfloat16* tb = reinterpret_cast<__nv_bfloat16*>(g_M4);
        #pragma unroll
        for (int qq = 0; qq < 4; ++qq) {
            int j = 4 * lane + qq;
            size_t bidx = ((((size_t)126 * 16 + (j >> 3)) * 4 + c) * 32 +
                           ((j & 7) | (kq << 3))) * 8 + r;
            tb[bidx] = __float2bfloat16_rn(pv[qq]);
        }
    }
}

// ---------------------------------------------------------------------------
// Prep B: emission sigmoid table.
// ---------------------------------------------------------------------------
__global__ void k_prepS(const float* __restrict__ lpx) {
    int i = blockIdx.x * 256 + threadIdx.x;
    if (i < D_ * A_) {
        float l = lpx[i];
        g_S2[i] = make_float2(1.0f / (1.0f + __expf(-l)),
                              1.0f / (1.0f + __expf(l)));
    }
}

// ---------------------------------------------------------------------------
// Prep C: softmax of u_log_p_a1 -> g_pa1; writes log_p_a1 output tail.
// ---------------------------------------------------------------------------
__global__ void k_pa1(const float* __restrict__ u, float* __restrict__ out,
                      int base, int out_size) {
    __shared__ float sred[4];
    int t = threadIdx.x, lane = t & 31, w = t >> 5;
    float v = u[t];
    float m = v;
    #pragma unroll
    for (int o = 16; o > 0; o >>= 1) m = fmaxf(m, __shfl_xor_sync(0xffffffffu, m, o));
    if (lane == 0) sred[w] = m;
    __syncthreads();
    m = fmaxf(fmaxf(sred[0], sred[1]), fmaxf(sred[2], sred[3]));
    __syncthreads();
    float e = __expf(v - m);
    float s = e;
    #pragma unroll
    for (int o = 16; o > 0; o >>= 1) s += __shfl_xor_sync(0xffffffffu, s, o);
    if (lane == 0) sred[w] = s;
    __syncthreads();
    s = sred[0] + sred[1] + sred[2] + sred[3];
    float lp = v - m - logf(s);
    g_pa1[t] = __expf(lp);
    int idx = base + t;
    if (idx < out_size) out[idx] = lp;
}

// ---------------------------------------------------------------------------
// Fuse GEMM: slot = blockIdx.x (0..125), p = slot>>1, x = slot&1.
// C[i][j] = sum_k T2p[i][k] * e(2p+1,k,x) * T2p1[k][j], fp32, FFMA2 inner.
// Block 256 (16x16 threads of 8x8 tiles). Output packed bf16 via smem staging.
// Dynamic smem: As[128][132] fp32 | Bs[128][128] fp32 | Es[128] fp32.
// ---------------------------------------------------------------------------
#define AP 132
#define BS_OFF (128 * AP)
#define ES_OFF (BS_OFF + 128 * 128)
#define MM_SMEM ((ES_OFF + 128) * 4)

__global__ void __launch_bounds__(256, 1) k_matmul() {
    extern __shared__ float sm[];
    float* As = sm;
    float* Bs = sm + BS_OFF;
    float* Es = sm + ES_OFF;

    const int slot = blockIdx.x;
    const int p = slot >> 1, xv = slot & 1;
    const int tid = threadIdx.x;

    const float* Am = g_Tf + (size_t)(2 * p) * 16384;
    const float* Bm = g_Tf + (size_t)(2 * p + 1) * 16384;

    if (tid < 128) {
        float2 sv = g_S2[(2 * p + 1) * A_ + tid];
        Es[tid] = xv ? sv.x : sv.y;
    }
    __syncthreads();

    for (int idx = tid; idx < 16384; idx += 256) {
        int i = idx >> 7, k = idx & 127;
        As[k * AP + i] = Am[idx] * Es[k];
        Bs[idx] = Bm[idx];
    }
    __syncthreads();

    const int tx = tid & 15, ty = tid >> 4;
    const int i0 = ty * 8, j0 = tx * 8;

    unsigned long long cc[8][4];
    #pragma unroll
    for (int mi = 0; mi < 8; ++mi)
        #pragma unroll
        for (int q = 0; q < 4; ++q) cc[mi][q] = 0ull;

    for (int kk = 0; kk < 128; ++kk) {
        float4 aA = *reinterpret_cast<const float4*>(&As[kk * AP + i0]);
        float4 aB = *reinterpret_cast<const float4*>(&As[kk * AP + i0 + 4]);
        const ulonglong2* bp =
            reinterpret_cast<const ulonglong2*>(&Bs[kk * 128 + j0]);
        ulonglong2 b01 = bp[0], b23 = bp[1];
        float am[8] = {aA.x, aA.y, aA.z, aA.w, aB.x, aB.y, aB.z, aB.w};
        #pragma unroll
        for (int mi = 0; mi < 8; ++mi) {
            unsigned long long aa;
            PACK_F32X2(aa, am[mi], am[mi]);
            FMA_F32X2(cc[mi][0], aa, b01.x);
            FMA_F32X2(cc[mi][1], aa, b01.y);
            FMA_F32X2(cc[mi][2], aa, b23.x);
            FMA_F32X2(cc[mi][3], aa, b23.y);
        }
    }
    __syncthreads();   // done reading As/Bs; reuse As region as bf16 staging

    __nv_bfloat16* stage = reinterpret_cast<__nv_bfloat16*>(sm);
    #pragma unroll
    for (int mi = 0; mi < 8; ++mi) {
        int i = i0 + mi;                      // k-role index in forward
        int lnhalf = (i >> 5) << 3;           // kq bits of lane
        int c = (i & 31) >> 3;
        int r = i & 7;
        #pragma unroll
        for (int q = 0; q < 4; ++q) {
            float lo, hi;
            UNPACK_F32X2(lo, hi, cc[mi][q]);
            int j = j0 + 2 * q;
            size_t li = ((((size_t)(j >> 3)) * 4 + c) * 32 +
                         ((j & 7) | lnhalf)) * 8 + r;
            stage[li] = __float2bfloat16_rn(lo);
            // j+1 has same (j>>3), (j&7)+1
            size_t li2 = ((((size_t)((j + 1) >> 3)) * 4 + c) * 32 +
                          (((j + 1) & 7) | lnhalf)) * 8 + r;
            stage[li2] = __float2bfloat16_rn(hi);
        }
    }
    __syncthreads();

    uint4* dst = g_M4 + (size_t)slot * 2048;
    const uint4* src = reinterpret_cast<const uint4*>(sm);
    for (int idx = tid; idx < 2048; idx += 256) dst[idx] = src[idx];
}

// ---------------------------------------------------------------------------
// Main forward recurrence over 64 fused steps. grid = B, block = 512.
// Same symmetric structure as R10: warp w owns j in [8w,8w+8) over all k;
// lane l: j = 8w+(l&7), k-quarter = l>>3; ONE barrier per step.
// Matrix slot per step s: s<63 -> 2s + x[b,2s+1]; s=63 -> 126 (tail).
// Emission per step s: e_{2s+2} (s<63) else e_127. Rescale every 8 steps.
// ---------------------------------------------------------------------------
__global__ void __launch_bounds__(512, 1) k_forward(const float* __restrict__ x,
                                                    float* __restrict__ out,
                                                    int out_size) {
    const int b = blockIdx.x;
    const int t = threadIdx.x;
    const int w = t >> 5, lane = t & 31;
    const int jown = 8 * w + (lane & 7);
    const int kq = lane >> 3;
    const int vq = kq * VP;
    const bool writer = (lane < 8);

    __shared__ __align__(16) float v_sh[2][4 * VP];
    __shared__ float s_red[16];
    __shared__ float sx[D_];

    if (t < D_) sx[t] = x[b * D_ + t];
    __syncthreads();

    float e_pref, acc = 0.f;
    {
        float2 s0 = g_S2[jown];
        float v0 = ((sx[0] > 0.5f) ? s0.x : s0.y) * g_pa1[jown];
        if (writer) v_sh[0][(jown >> 5) * VP + (jown & 31)] = v0;
        float2 s2 = g_S2[2 * A_ + jown];       // e for step 0 = e_2
        e_pref = (sx[2] > 0.5f) ? s2.x : s2.y;
    }
    __syncthreads();   // v_sh[0] ready

#define SLOT(S) (((S) < 63) ? (2 * (S) + ((sx[2 * (S) + 1] > 0.5f) ? 1 : 0)) : 126)

    // per-(warp,lane) base in uint4 units; +slot*2048 per matrix; +c*32
    const uint4* Tb = g_M4 + (size_t)w * 128 + lane;

    uint4 TA[4], TB[4];
    {
        const uint4* tp = Tb + (size_t)SLOT(0) * 2048;
        #pragma unroll
        for (int c = 0; c < 4; ++c) TA[c] = tp[c * 32];
    }

    float vfin = 0.f;

#define PREFETCH_T(DST, SL) do {                                             \
        const uint4* _tp = Tb + (size_t)(SL) * 2048;                         \
        _Pragma("unroll")                                                    \
        for (int c = 0; c < 4; ++c) (DST)[c] = _tp[c * 32];                  \
    } while (0)

#define CHUNK(R, OFF, ACC) do {                                              \
        float4 va = *reinterpret_cast<const float4*>(&vr[(OFF)]);            \
        float4 vb = *reinterpret_cast<const float4*>(&vr[(OFF) + 4]);        \
        ACC = fmaf(__uint_as_float((R).x << 16),         va.x, ACC);         \
        ACC = fmaf(__uint_as_float((R).x & 0xffff0000u), va.y, ACC);         \
        ACC = fmaf(__uint_as_float((R).y << 16),         va.z, ACC);         \
        ACC = fmaf(__uint_as_float((R).y & 0xffff0000u), va.w, ACC);         \
        ACC = fmaf(__uint_as_float((R).z << 16),         vb.x, ACC);         \
        ACC = fmaf(__uint_as_float((R).z & 0xffff0000u), vb.y, ACC);         \
        ACC = fmaf(__uint_as_float((R).w << 16),         vb.z, ACC);         \
        ACC = fmaf(__uint_as_float((R).w & 0xffff0000u), vb.w, ACC);         \
    } while (0)

#define STEP(DD, TARR) do {                                                  \
        const int rb = (DD) & 1, wb = ((DD) + 1) & 1;                        \
        const float* vr = &v_sh[rb][vq];                                     \
        float acc0 = 0.f, acc1 = 0.f;                                        \
        CHUNK((TARR)[0], 0,  acc0);                                          \
        CHUNK((TARR)[1], 8,  acc1);                                          \
        CHUNK((TARR)[2], 16, acc0);                                          \
        CHUNK((TARR)[3], 24, acc1);                                          \
        float sum = acc0 + acc1;                                             \
        sum += __shfl_xor_sync(0xffffffffu, sum, 8);                         \
        sum += __shfl_xor_sync(0xffffffffu, sum, 16);                        \
        float val = sum * e_pref;                                            \
        if (writer) v_sh[wb][(jown >> 5) * VP + (jown & 31)] = val;          \
        vfin = val;                                                          \
        {   /* prefetch emission for next step */                            \
            int de = ((DD) + 1 < 63) ? (2 * (DD) + 4) : 127;                 \
            float2 sn = g_S2[de * A_ + jown];                                \
            e_pref = (sx[de] > 0.5f) ? sn.x : sn.y;                          \
        }                                                                    \
        const bool resc = (((DD) & 7) == 7) && ((DD) != 63);                 \
        if (resc) {                                                          \
            float m = val;                                                   \
            m = fmaxf(m, __shfl_xor_sync(0xffffffffu, m, 1));                \
            m = fmaxf(m, __shfl_xor_sync(0xffffffffu, m, 2));                \
            m = fmaxf(m, __shfl_xor_sync(0xffffffffu, m, 4));                \
            if (lane == 0) s_red[w] = m;                                     \
        }                                                                    \
        __syncthreads();   /* publishes v_sh[wb] (+ s_red on resc steps) */  \
        if (resc) {                                                          \
            float mm = fmaxf(                                                \
                fmaxf(fmaxf(s_red[0],  s_red[1]),  fmaxf(s_red[2],  s_red[3])),  \
                fmaxf(fmaxf(s_red[4],  s_red[5]),  fmaxf(s_red[6],  s_red[7]))); \
            mm = fmaxf(mm, fmaxf(                                            \
                fmaxf(fmaxf(s_red[8],  s_red[9]),  fmaxf(s_red[10], s_red[11])), \
                fmaxf(fmaxf(s_red[12], s_red[13]), fmaxf(s_red[14], s_red[15])))); \
            e_pref *= (1.0f / mm);                                           \
            acc += __logf(mm);                                               \
        }                                                                    \
    } while (0)

    for (int s = 0; s < NSTEP; s += 2) {
        PREFETCH_T(TB, SLOT(s + 1));
        STEP(s, TA);
        PREFETCH_T(TA, SLOT(s + 2));   // SLOT(64) -> 126, harmless
        STEP(s + 1, TB);
    }

#undef STEP
#undef CHUNK
#undef PREFETCH_T
#undef SLOT

    // final: log_px[b] = acc + log(sum_j v_final[j])
    float sv = vfin;
    sv += __shfl_xor_sync(0xffffffffu, sv, 1);
    sv += __shfl_xor_sync(0xffffffffu, sv, 2);
    sv += __shfl_xor_sync(0xffffffffu, sv, 4);
    if (lane == 0) s_red[w] = sv;
    __syncthreads();
    float tot = (((s_red[0]  + s_red[1])  + (s_red[2]  + s_red[3]))
              +  ((s_red[4]  + s_red[5])  + (s_red[6]  + s_red[7])))
              + (((s_red[8]  + s_red[9])  + (s_red[10] + s_red[11]))
              +  ((s_red[12] + s_red[13]) + (s_red[14] + s_red[15])));
    float res = acc + __logf(tot);
    if (writer) {
        int idx = b * A_ + jown;
        if (idx < out_size) out[idx] = res;
    }
}

// ---------------------------------------------------------------------------
extern "C" void kernel_launch(void* const* d_in, const int* in_sizes, int n_in,
                              void* d_out, int out_size) {
    const float* x     = (const float*)d_in[0];   // [B, D]
    const float* u_pa1 = (const float*)d_in[1];   // [1,1,1,A]
    const float* u_T   = (const float*)d_in[2];   // [D-1, A, A]
    const float* lpx   = (const float*)d_in[3];   // [1, D, 1, A]
    float* out = (float*)d_out;

    int B = in_sizes[0] / D_;
    if (B > MAXB) B = MAXB;

    static bool attr_set = false;
    if (!attr_set) {
        cudaFuncSetAttribute(k_matmul,
                             cudaFuncAttributeMaxDynamicSharedMemorySize,
                             MM_SMEM);
        attr_set = true;
    }

    k_prepT<<<(DM1 * A_ + 7) / 8, 256>>>(u_T);
    k_prepS<<<(D_ * A_ + 255) / 256, 256>>>(lpx);
    k_pa1<<<1, 128>>>(u_pa1, out, B * A_, out_size);
    k_matmul<<<126, 256, MM_SMEM>>>();
    k_forward<<<B, 512>>>(x, out, out_size);
}